// round 3
// baseline (speedup 1.0000x reference)
#include <cuda_runtime.h>

#define HIDDEN 32
#define FF 40
#define TSTEPS 512
#define BATCH 16384
#define HALF_FF 20          /* j-columns per thread (FF split 2 ways) */

typedef unsigned long long u64;
typedef unsigned int u32;

__device__ __forceinline__ u64 pk(float a, float b) {
    u64 r; asm("mov.b64 %0,{%1,%2};" : "=l"(r) : "f"(a), "f"(b)); return r;
}
__device__ __forceinline__ void upk(u64 v, float& a, float& b) {
    asm("mov.b64 {%0,%1},%2;" : "=f"(a), "=f"(b) : "l"(v));
}
__device__ __forceinline__ u64 f2fma(u64 a, u64 b, u64 c) {
    u64 d; asm("fma.rn.f32x2 %0,%1,%2,%3;" : "=l"(d) : "l"(a), "l"(b), "l"(c)); return d;
}
__device__ __forceinline__ u64 f2add(u64 a, u64 b) {
    u64 d; asm("add.rn.f32x2 %0,%1,%2;" : "=l"(d) : "l"(a), "l"(b)); return d;
}
// sigmoid via ex2/rcp approx (~1e-6 rel err, well inside 1e-3 budget)
__device__ __forceinline__ float sigm(float x) {
    float e, r;
    asm("ex2.approx.ftz.f32 %0,%1;" : "=f"(e) : "f"(x * -1.4426950408889634f));
    asm("rcp.approx.ftz.f32 %0,%1;" : "=f"(r) : "f"(1.0f + e));
    return r;
}
// lane-pair butterfly for a packed f32x2 value
__device__ __forceinline__ u64 shflx1_u64(u64 v) {
    u32 lo, hi;
    asm("mov.b64 {%0,%1},%2;" : "=r"(lo), "=r"(hi) : "l"(v));
    lo = __shfl_xor_sync(0xffffffffu, lo, 1);
    hi = __shfl_xor_sync(0xffffffffu, hi, 1);
    u64 r; asm("mov.b64 %0,{%1,%2};" : "=l"(r) : "r"(lo), "r"(hi)); return r;
}

__global__ void __launch_bounds__(32) rnn_split2_kernel(
    const float* __restrict__ inp,
    const float* __restrict__ W1hh, const float* __restrict__ b1hh,
    const float* __restrict__ W2hh, const float* __restrict__ b2hh,
    const float* __restrict__ W1ho, const float* __restrict__ b1ho,
    const float* __restrict__ W2ho, const float* __restrict__ b2ho,
    float* __restrict__ out)
{
    // Raw row-major weight copies in smem. Row strides (160B / 128B) and the
    // half-offsets (20 floats = 80B) are all 16B-aligned -> LDS.128 directly.
    __shared__ __align__(16) float sW1hh[33 * FF];
    __shared__ __align__(16) float sW1ho[33 * FF];
    __shared__ __align__(16) float sW2hh[FF * HIDDEN];
    __shared__ __align__(16) float sW2ho[FF];
    __shared__ __align__(16) float sb1hh[FF];
    __shared__ __align__(16) float sb1ho[FF];
    __shared__ __align__(16) float sb2hh[HIDDEN];

    const int tid = threadIdx.x;
    for (int i = tid; i < 33 * FF; i += 32) { sW1hh[i] = W1hh[i]; sW1ho[i] = W1ho[i]; }
    for (int i = tid; i < FF * HIDDEN; i += 32) sW2hh[i] = W2hh[i];
    // FF=40 > 32 lanes: MUST be strided loops (R2 bug: `if (tid < FF)` left
    // elements 32..39 uninitialized with a 32-thread block).
    for (int i = tid; i < FF; i += 32) {
        sW2ho[i] = W2ho[i]; sb1hh[i] = b1hh[i]; sb1ho[i] = b1ho[i];
    }
    for (int i = tid; i < HIDDEN; i += 32) sb2hh[i] = b2hh[i];
    const float bias_o = b2ho[0];
    __syncthreads();

    const int g    = blockIdx.x * 32 + tid;   // 32768 threads
    const int e    = g >> 1;                  // batch element
    const int half = g & 1;                   // FF half: columns [20h, 20h+20)
    const float* __restrict__ ip = inp + (size_t)e * TSTEPS;
    float* __restrict__ op = out + (size_t)e * TSTEPS;

    const int joff = half * HALF_FF;          // 80B offset, 16B aligned

    // recurrent state fully in registers
    float h[HIDDEN];
    #pragma unroll
    for (int i = 0; i < HIDDEN; i++) h[i] = 0.0f;

    float u = ip[0];

    #pragma unroll 1
    for (int t = 0; t < TSTEPS; t++) {
        float u_next = ip[(t + 1) & (TSTEPS - 1)];   // prefetch (wraps harmlessly)

        // ---- layer 1, both heads, this thread's 20 j-columns (10 f32x2) ----
        u64 zhh[10], zho[10];
        {
            const u64* bh = (const u64*)(sb1hh + joff);
            const u64* bo = (const u64*)(sb1ho + joff);
            #pragma unroll
            for (int jp = 0; jp < 10; jp++) { zhh[jp] = bh[jp]; zho[jp] = bo[jp]; }
        }
        #pragma unroll
        for (int i = 0; i < 33; i++) {
            float c = (i < HIDDEN) ? h[i] : u;
            u64 cd = pk(c, c);
            const ulonglong2* wa = (const ulonglong2*)(sW1hh + i * FF + joff);
            const ulonglong2* wb = (const ulonglong2*)(sW1ho + i * FF + joff);
            #pragma unroll
            for (int q = 0; q < 5; q++) {
                ulonglong2 A = wa[q];
                zhh[2 * q]     = f2fma(cd, A.x, zhh[2 * q]);
                zhh[2 * q + 1] = f2fma(cd, A.y, zhh[2 * q + 1]);
                ulonglong2 Bv = wb[q];
                zho[2 * q]     = f2fma(cd, Bv.x, zho[2 * q]);
                zho[2 * q + 1] = f2fma(cd, Bv.y, zho[2 * q + 1]);
            }
        }

        // ---- s = sigmoid(zhh) (registers) ----
        float s[HALF_FF];
        #pragma unroll
        for (int jp = 0; jp < 10; jp++) {
            float a, b; upk(zhh[jp], a, b);
            s[2 * jp] = sigm(a); s[2 * jp + 1] = sigm(b);
        }

        // ---- output head: partial dot of sigmoid(zho) with W2ho half ----
        {
            u64 acc = 0ull;
            const ulonglong2* wo = (const ulonglong2*)(sW2ho + joff);
            #pragma unroll
            for (int q = 0; q < 5; q++) {
                float a0, b0; upk(zho[2 * q], a0, b0);
                float a1, b1; upk(zho[2 * q + 1], a1, b1);
                ulonglong2 W = wo[q];
                acc = f2fma(pk(sigm(a0), sigm(b0)), W.x, acc);
                acc = f2fma(pk(sigm(a1), sigm(b1)), W.y, acc);
            }
            float a, b; upk(acc, a, b);
            float o_part = a + b;
            float o = o_part + __shfl_xor_sync(0xffffffffu, o_part, 1);
            if (half == 0) op[t] = o + bias_o;
        }

        // ---- layer 2 partial: h_new += s_k * W2hh[k,:] over this half's k ----
        u64 hn[16];
        {
            const u64* b2 = (const u64*)sb2hh;
            #pragma unroll
            for (int p = 0; p < 16; p++) hn[p] = (half == 0) ? b2[p] : 0ull;
        }
        #pragma unroll
        for (int kk = 0; kk < HALF_FF; kk++) {
            u64 sd = pk(s[kk], s[kk]);
            const ulonglong2* w = (const ulonglong2*)(sW2hh + (joff + kk) * HIDDEN);
            #pragma unroll
            for (int q = 0; q < 8; q++) {
                ulonglong2 W = w[q];
                hn[2 * q]     = f2fma(sd, W.x, hn[2 * q]);
                hn[2 * q + 1] = f2fma(sd, W.y, hn[2 * q + 1]);
            }
        }

        // ---- pair butterfly: both lanes get the full h_new ----
        #pragma unroll
        for (int p = 0; p < 16; p++) {
            u64 full = f2add(hn[p], shflx1_u64(hn[p]));
            upk(full, h[2 * p], h[2 * p + 1]);
        }

        u = u_next;
    }
}

extern "C" void kernel_launch(void* const* d_in, const int* in_sizes, int n_in,
                              void* d_out, int out_size) {
    const float* inp  = (const float*)d_in[0];
    const float* W1hh = (const float*)d_in[1];
    const float* b1hh = (const float*)d_in[2];
    const float* W2hh = (const float*)d_in[3];
    const float* b2hh = (const float*)d_in[4];
    const float* W1ho = (const float*)d_in[5];
    const float* b1ho = (const float*)d_in[6];
    const float* W2ho = (const float*)d_in[7];
    const float* b2ho = (const float*)d_in[8];
    float* out = (float*)d_out;

    dim3 grid(2 * BATCH / 32);   // 1024 single-warp blocks -> ~7 warps/SM on 148 SMs
    dim3 block(32);
    rnn_split2_kernel<<<grid, block>>>(inp, W1hh, b1hh, W2hh, b2hh,
                                       W1ho, b1ho, W2ho, b2ho, out);
}

// round 4
// speedup vs baseline: 4.1346x; 4.1346x over previous
#include <cuda_runtime.h>

#define HIDDEN 32
#define FF 40
#define TSTEPS 512
#define BATCH 16384
#define HALF_FF 20          /* j-columns per thread (FF split 2 ways) */

typedef unsigned long long u64;
typedef unsigned int u32;

__device__ __forceinline__ u64 pk(float a, float b) {
    u64 r; asm("mov.b64 %0,{%1,%2};" : "=l"(r) : "f"(a), "f"(b)); return r;
}
__device__ __forceinline__ void upk(u64 v, float& a, float& b) {
    asm("mov.b64 {%0,%1},%2;" : "=f"(a), "=f"(b) : "l"(v));
}
__device__ __forceinline__ u64 f2fma(u64 a, u64 b, u64 c) {
    u64 d; asm("fma.rn.f32x2 %0,%1,%2,%3;" : "=l"(d) : "l"(a), "l"(b), "l"(c)); return d;
}
__device__ __forceinline__ u64 f2add(u64 a, u64 b) {
    u64 d; asm("add.rn.f32x2 %0,%1,%2;" : "=l"(d) : "l"(a), "l"(b)); return d;
}
// sigmoid via ex2/rcp approx (~1e-6 rel err, well inside 1e-3 budget)
__device__ __forceinline__ float sigm(float x) {
    float e, r;
    asm("ex2.approx.ftz.f32 %0,%1;" : "=f"(e) : "f"(x * -1.4426950408889634f));
    asm("rcp.approx.ftz.f32 %0,%1;" : "=f"(r) : "f"(1.0f + e));
    return r;
}
__device__ __forceinline__ u64 shflx1_u64(u64 v) {
    u32 lo, hi;
    asm("mov.b64 {%0,%1},%2;" : "=r"(lo), "=r"(hi) : "l"(v));
    lo = __shfl_xor_sync(0xffffffffu, lo, 1);
    hi = __shfl_xor_sync(0xffffffffu, hi, 1);
    u64 r; asm("mov.b64 %0,{%1,%2};" : "=l"(r) : "r"(lo), "r"(hi)); return r;
}

// cap regs at 204 (65536/(32*10)) -- guards against the R3 255-reg spill blowup
__global__ void __launch_bounds__(32, 10) rnn_hybrid_kernel(
    const float* __restrict__ inp,
    const float* __restrict__ W1hh, const float* __restrict__ b1hh,
    const float* __restrict__ W2hh, const float* __restrict__ b2hh,
    const float* __restrict__ W1ho, const float* __restrict__ b1ho,
    const float* __restrict__ W2ho, const float* __restrict__ b2ho,
    float* __restrict__ out)
{
    // Row-major weight copies; row strides (160B/128B) and the 80B half-offset
    // are 16B-aligned -> LDS.128 directly.
    __shared__ __align__(16) float sW1hh[33 * FF];
    __shared__ __align__(16) float sW1ho[33 * FF];
    __shared__ __align__(16) float sW2hh[FF * HIDDEN];
    __shared__ __align__(16) float sW2ho[FF];
    __shared__ __align__(16) float sb1hh[FF];
    __shared__ __align__(16) float sb1ho[FF];
    __shared__ __align__(16) float sb2hh[HIDDEN];
    // Per-thread state columns (lane-stride-1 => conflict-free, thread-private):
    // cst[p][tid] = packed (h[2p], h[2p+1]);  sst[kk][tid] = packed sigmoid pair.
    __shared__ u64 cst[16 * 32];
    __shared__ u64 sst[10 * 32];

    const int tid = threadIdx.x;
    for (int i = tid; i < 33 * FF; i += 32) { sW1hh[i] = W1hh[i]; sW1ho[i] = W1ho[i]; }
    for (int i = tid; i < FF * HIDDEN; i += 32) sW2hh[i] = W2hh[i];
    for (int i = tid; i < FF; i += 32) {        // strided: FF=40 > 32 lanes
        sW2ho[i] = W2ho[i]; sb1hh[i] = b1hh[i]; sb1ho[i] = b1ho[i];
    }
    for (int i = tid; i < HIDDEN; i += 32) sb2hh[i] = b2hh[i];
    const float bias_o = b2ho[0];
    __syncthreads();

    const int g    = blockIdx.x * 32 + tid;   // 32768 threads
    const int e    = g >> 1;                  // batch element
    const int half = g & 1;                   // FF half: columns [20h, 20h+20)
    const float* __restrict__ ip = inp + (size_t)e * TSTEPS;
    float* __restrict__ op = out + (size_t)e * TSTEPS;
    const int joff = half * HALF_FF;          // 80B offset, 16B aligned

    // h0 = 0
    #pragma unroll
    for (int p = 0; p < 16; p++) cst[p * 32 + tid] = 0ull;

    float u = ip[0];

    #pragma unroll 1
    for (int t = 0; t < TSTEPS; t++) {
        float u_next = ip[(t + 1) & (TSTEPS - 1)];

        // ---- layer 1, both heads: this thread's 20 j-columns (10 f32x2) ----
        u64 zhh[10], zho[10];
        {
            const ulonglong2* bh = (const ulonglong2*)(sb1hh + joff);
            const ulonglong2* bo = (const ulonglong2*)(sb1ho + joff);
            #pragma unroll
            for (int q = 0; q < 5; q++) {
                ulonglong2 B1 = bh[q]; zhh[2 * q] = B1.x; zhh[2 * q + 1] = B1.y;
                ulonglong2 B2 = bo[q]; zho[2 * q] = B2.x; zho[2 * q + 1] = B2.y;
            }
        }
        #pragma unroll 2
        for (int p = 0; p < 16; p++) {
            float c0, c1; upk(cst[p * 32 + tid], c0, c1);
            #pragma unroll
            for (int s2 = 0; s2 < 2; s2++) {
                float c = (s2 == 0) ? c0 : c1;
                u64 cd = pk(c, c);
                const ulonglong2* wa = (const ulonglong2*)(sW1hh + (2 * p + s2) * FF + joff);
                const ulonglong2* wb = (const ulonglong2*)(sW1ho + (2 * p + s2) * FF + joff);
                #pragma unroll
                for (int q = 0; q < 5; q++) {
                    ulonglong2 A = wa[q];
                    zhh[2 * q]     = f2fma(cd, A.x, zhh[2 * q]);
                    zhh[2 * q + 1] = f2fma(cd, A.y, zhh[2 * q + 1]);
                    ulonglong2 Bv = wb[q];
                    zho[2 * q]     = f2fma(cd, Bv.x, zho[2 * q]);
                    zho[2 * q + 1] = f2fma(cd, Bv.y, zho[2 * q + 1]);
                }
            }
        }
        {   // row i=32: the input u
            u64 cd = pk(u, u);
            const ulonglong2* wa = (const ulonglong2*)(sW1hh + 32 * FF + joff);
            const ulonglong2* wb = (const ulonglong2*)(sW1ho + 32 * FF + joff);
            #pragma unroll
            for (int q = 0; q < 5; q++) {
                ulonglong2 A = wa[q];
                zhh[2 * q]     = f2fma(cd, A.x, zhh[2 * q]);
                zhh[2 * q + 1] = f2fma(cd, A.y, zhh[2 * q + 1]);
                ulonglong2 Bv = wb[q];
                zho[2 * q]     = f2fma(cd, Bv.x, zho[2 * q]);
                zho[2 * q + 1] = f2fma(cd, Bv.y, zho[2 * q + 1]);
            }
        }

        // ---- s = sigmoid(zhh) -> packed pairs in smem ----
        #pragma unroll
        for (int jp = 0; jp < 10; jp++) {
            float a, b; upk(zhh[jp], a, b);
            sst[jp * 32 + tid] = pk(sigm(a), sigm(b));
        }

        // ---- output head: partial dot sigmoid(zho) . W2ho[half] ----
        {
            u64 acc = 0ull;
            const ulonglong2* wo = (const ulonglong2*)(sW2ho + joff);
            #pragma unroll
            for (int q = 0; q < 5; q++) {
                float a0, b0; upk(zho[2 * q], a0, b0);
                float a1, b1; upk(zho[2 * q + 1], a1, b1);
                ulonglong2 W = wo[q];
                acc = f2fma(pk(sigm(a0), sigm(b0)), W.x, acc);
                acc = f2fma(pk(sigm(a1), sigm(b1)), W.y, acc);
            }
            float a, b; upk(acc, a, b);
            float o_part = a + b;
            float o = o_part + __shfl_xor_sync(0xffffffffu, o_part, 1);
            if (half == 0) op[t] = o + bias_o;
        }

        // ---- layer 2 partial: hn += s_k * W2hh[k,:] over this half's 20 k ----
        u64 hn[16];
        {
            const u64* b2 = (const u64*)sb2hh;
            #pragma unroll
            for (int p = 0; p < 16; p++) hn[p] = (half == 0) ? b2[p] : 0ull;
        }
        #pragma unroll 1
        for (int kk = 0; kk < 10; kk++) {
            float s0, s1; upk(sst[kk * 32 + tid], s0, s1);
            const ulonglong2* w0 = (const ulonglong2*)(sW2hh + (joff + 2 * kk) * HIDDEN);
            const ulonglong2* w1 = (const ulonglong2*)(sW2hh + (joff + 2 * kk + 1) * HIDDEN);
            u64 sd0 = pk(s0, s0), sd1 = pk(s1, s1);
            #pragma unroll
            for (int q = 0; q < 8; q++) {
                ulonglong2 W0 = w0[q];
                hn[2 * q]     = f2fma(sd0, W0.x, hn[2 * q]);
                hn[2 * q + 1] = f2fma(sd0, W0.y, hn[2 * q + 1]);
            }
            #pragma unroll
            for (int q = 0; q < 8; q++) {
                ulonglong2 W1 = w1[q];
                hn[2 * q]     = f2fma(sd1, W1.x, hn[2 * q]);
                hn[2 * q + 1] = f2fma(sd1, W1.y, hn[2 * q + 1]);
            }
        }

        // ---- pair butterfly + state writeback ----
        #pragma unroll
        for (int p = 0; p < 16; p++) {
            cst[p * 32 + tid] = f2add(hn[p], shflx1_u64(hn[p]));
        }

        u = u_next;
    }
}

extern "C" void kernel_launch(void* const* d_in, const int* in_sizes, int n_in,
                              void* d_out, int out_size) {
    const float* inp  = (const float*)d_in[0];
    const float* W1hh = (const float*)d_in[1];
    const float* b1hh = (const float*)d_in[2];
    const float* W2hh = (const float*)d_in[3];
    const float* b2hh = (const float*)d_in[4];
    const float* W1ho = (const float*)d_in[5];
    const float* b1ho = (const float*)d_in[6];
    const float* W2ho = (const float*)d_in[7];
    const float* b2ho = (const float*)d_in[8];
    float* out = (float*)d_out;

    dim3 grid(2 * BATCH / 32);   // 1024 single-warp blocks -> ~7 warps/SM
    dim3 block(32);
    rnn_hybrid_kernel<<<grid, block>>>(inp, W1hh, b1hh, W2hh, b2hh,
                                       W1ho, b1ho, W2ho, b2ho, out);
}